// round 9
// baseline (speedup 1.0000x reference)
#include <cuda_runtime.h>
#include <cuda_fp16.h>
#include <mma.h>

using namespace nvcuda;

#define NN 100000
#define NE 1600000
#define IND 75
#define H 64
#define HB 16

// Scratch (allocation-free rule: __device__ globals)
__device__ __align__(256) float g_hA[NN * H];
__device__ __align__(256) float g_hB[NN * H];
__device__ __align__(256) float g_P[NN * H];
__device__ __align__(256) float g_agg[NN * H];

// ---------------------------------------------------------------------------
// proj: out = x @ W(75x64) + b     (run once)
// ---------------------------------------------------------------------------
__global__ __launch_bounds__(256) void proj_kernel(const float* __restrict__ x,
                                                   const float* __restrict__ w,
                                                   const float* __restrict__ b,
                                                   float* __restrict__ out) {
    __shared__ float sW[IND][H];
    __shared__ float sA[32][IND + 1];
    for (int i = threadIdx.x; i < IND * H; i += 256) sW[i / H][i % H] = w[i];

    const int lane = threadIdx.x & 31, wid = threadIdx.x >> 5;
    const int nl = lane & 3, cg = lane >> 2;
    const int myn = wid * 4 + nl;
    const float4 bb0 = *(const float4*)&b[cg * 8];
    const float4 bb1 = *(const float4*)&b[cg * 8 + 4];

    for (int tile = blockIdx.x; tile < NN / 32; tile += gridDim.x) {
        const int base = tile * 32;
        __syncthreads();
        for (int i = threadIdx.x; i < 32 * IND; i += 256)
            sA[i / IND][i % IND] = x[(size_t)base * IND + i];
        __syncthreads();

        float acc[8] = {bb0.x, bb0.y, bb0.z, bb0.w, bb1.x, bb1.y, bb1.z, bb1.w};
#pragma unroll 5
        for (int k = 0; k < IND; k++) {
            const float a = sA[myn][k];
            const float4 w0 = *(const float4*)&sW[k][cg * 8];
            const float4 w1 = *(const float4*)&sW[k][cg * 8 + 4];
            acc[0] += a * w0.x; acc[1] += a * w0.y; acc[2] += a * w0.z; acc[3] += a * w0.w;
            acc[4] += a * w1.x; acc[5] += a * w1.y; acc[6] += a * w1.z; acc[7] += a * w1.w;
        }
        const size_t o = (size_t)(base + myn) * H + cg * 8;
        *(float4*)&out[o]     = make_float4(acc[0], acc[1], acc[2], acc[3]);
        *(float4*)&out[o + 4] = make_float4(acc[4], acc[5], acc[6], acc[7]);
    }
}

// ---------------------------------------------------------------------------
// Split-fp16 helpers: v = hi + lo, hi/lo fp16 -> ~22 mantissa bits.
// ---------------------------------------------------------------------------
__device__ __forceinline__ void split2(float v0, float v1, __half2& hh, __half2& hl) {
    __half h0 = __float2half(v0), h1 = __float2half(v1);
    hh = __halves2half2(h0, h1);
    hl = __halves2half2(__float2half(v0 - __half2float(h0)),
                        __float2half(v1 - __half2float(h1)));
}

// ---------------------------------------------------------------------------
// pk (HMMA): P = h @ W2h(64x64) + b2, and zero agg (fused).
// Block = 32-node x 64-col tile; 8 warps, each owns one m16n16 output tile.
// Split-fp16: P ~= Ah@Wh + Ah@Wl + Al@Wh (fp32 accum).
// ---------------------------------------------------------------------------
__global__ __launch_bounds__(256) void pk_kernel(const float* __restrict__ h,
                                                 const float* __restrict__ w,
                                                 const float* __restrict__ b,
                                                 float* __restrict__ P,
                                                 float* __restrict__ agg) {
    __shared__ __half sWh[H * H], sWl[H * H];      // 8192 B each
    __shared__ __half sAh[32 * 16], sAl[32 * 16];  // 1024 B each
    __shared__ float  sOut[8][16 * 16];            // 8192 B
    __shared__ float  sBias[H];

    for (int i = threadIdx.x; i < H * H; i += 256) {
        float v = w[i];
        __half hi = __float2half(v);
        sWh[i] = hi;
        sWl[i] = __float2half(v - __half2float(hi));
    }
    if (threadIdx.x < H) sBias[threadIdx.x] = b[threadIdx.x];

    const int wid = threadIdx.x >> 5, lane = threadIdx.x & 31;
    const int warp_m = wid >> 2, warp_n = wid & 3;   // 2 x 4 warp grid

    const int stg_r = (threadIdx.x * 2) >> 4;        // staging coords
    const int stg_c = (threadIdx.x * 2) & 15;

    for (int tile = blockIdx.x; tile < NN / 32; tile += gridDim.x) {
        const int nbase = tile * 32;
        wmma::fragment<wmma::accumulator, 16, 16, 16, float> fc;
        wmma::fill_fragment(fc, 0.f);

#pragma unroll
        for (int kc = 0; kc < 4; kc++) {
            __syncthreads();
            {   // stage A chunk [32][16] as hi/lo
                const float* sp = h + (size_t)(nbase + stg_r) * H + kc * 16 + stg_c;
                __half2 hh, hl;
                split2(sp[0], sp[1], hh, hl);
                *(__half2*)&sAh[stg_r * 16 + stg_c] = hh;
                *(__half2*)&sAl[stg_r * 16 + stg_c] = hl;
            }
            __syncthreads();

            wmma::fragment<wmma::matrix_a, 16, 16, 16, __half, wmma::row_major> fah, fal;
            wmma::load_matrix_sync(fah, &sAh[warp_m * 16 * 16], 16);
            wmma::load_matrix_sync(fal, &sAl[warp_m * 16 * 16], 16);
            wmma::fragment<wmma::matrix_b, 16, 16, 16, __half, wmma::row_major> fwh, fwl;
            wmma::load_matrix_sync(fwh, &sWh[(kc * 16) * H + warp_n * 16], H);
            wmma::load_matrix_sync(fwl, &sWl[(kc * 16) * H + warp_n * 16], H);
            wmma::mma_sync(fc, fah, fwh, fc);
            wmma::mma_sync(fc, fah, fwl, fc);
            wmma::mma_sync(fc, fal, fwh, fc);
        }

        wmma::store_matrix_sync(sOut[wid], fc, 16, wmma::mem_row_major);
        __syncwarp();
        {
            const int r = lane >> 1, c = (lane & 1) * 8;
            const int node = nbase + warp_m * 16 + r;
            const int col = warp_n * 16 + c;
            float4 v0 = *(float4*)&sOut[wid][r * 16 + c];
            float4 v1 = *(float4*)&sOut[wid][r * 16 + c + 4];
            const float* bp = &sBias[col];
            v0.x += bp[0]; v0.y += bp[1]; v0.z += bp[2]; v0.w += bp[3];
            v1.x += bp[4]; v1.y += bp[5]; v1.z += bp[6]; v1.w += bp[7];
            float* op = P + (size_t)node * H + col;
            *(float4*)op = v0;
            *(float4*)(op + 4) = v1;
        }
        {   // zero agg for this tile: 2048 floats / 256 thr = 2 float4 each
            const float4 z4 = make_float4(0.f, 0.f, 0.f, 0.f);
            float4* ap = (float4*)(agg + (size_t)nbase * H) + threadIdx.x * 2;
            ap[0] = z4; ap[1] = z4;
        }
    }
}

// ---------------------------------------------------------------------------
// edge (HMMA, from R8): warp handles 16 edges; eattr tile -> fp16 -> wmma
// against register-resident W2e; scatter with red.global.add.v4.
// ---------------------------------------------------------------------------
__global__ __launch_bounds__(256) void edge_kernel(const int* __restrict__ esrc,
                                                   const int* __restrict__ edst,
                                                   const float* __restrict__ eattr,
                                                   const float* __restrict__ w2e,
                                                   const float* __restrict__ P,
                                                   float* __restrict__ agg) {
    __shared__ __half sW[HB * H];              // 2048 B
    __shared__ __half sA[8][HB * HB];          // 8 x 512 B
    __shared__ float  sB[8][HB * H];           // 8 x 4096 B

    for (int i = threadIdx.x; i < HB * H; i += 256) sW[i] = __float2half(w2e[i]);
    __syncthreads();

    const int lane = threadIdx.x & 31, wid = threadIdx.x >> 5;
    const int half = lane >> 4, hl = lane & 15;
    const int cbase = hl * 4;

    wmma::fragment<wmma::matrix_b, 16, 16, 16, __half, wmma::row_major> fw[4];
#pragma unroll
    for (int nt = 0; nt < 4; nt++)
        wmma::load_matrix_sync(fw[nt], &sW[nt * 16], H);

    __half* const myA = sA[wid];
    float*  const myB = sB[wid];
    const int arow = lane >> 1, acol = (lane & 1) * 8;

    const int gw = blockIdx.x * 8 + wid;
    const int nw = gridDim.x * 8;

    for (int t = gw; t < NE / 16; t += nw) {
        const int ebase = t * 16;
        {
            const float4* src = (const float4*)(eattr + (size_t)(ebase + arow) * HB + acol);
            const float4 v0 = src[0], v1 = src[1];
            __half2 h0 = __floats2half2_rn(v0.x, v0.y);
            __half2 h1 = __floats2half2_rn(v0.z, v0.w);
            __half2 h2 = __floats2half2_rn(v1.x, v1.y);
            __half2 h3 = __floats2half2_rn(v1.z, v1.w);
            uint4 pk;
            pk.x = *(unsigned*)&h0; pk.y = *(unsigned*)&h1;
            pk.z = *(unsigned*)&h2; pk.w = *(unsigned*)&h3;
            *(uint4*)(myA + arow * HB + acol) = pk;
        }
        __syncwarp();

        wmma::fragment<wmma::matrix_a, 16, 16, 16, __half, wmma::row_major> fa;
        wmma::load_matrix_sync(fa, myA, HB);
#pragma unroll
        for (int nt = 0; nt < 4; nt++) {
            wmma::fragment<wmma::accumulator, 16, 16, 16, float> fc;
            wmma::fill_fragment(fc, 0.f);
            wmma::mma_sync(fc, fa, fw[nt], fc);
            wmma::store_matrix_sync(&myB[nt * 16], fc, H, wmma::mem_row_major);
        }
        __syncwarp();

#pragma unroll
        for (int r = 0; r < 8; r++) {
            const int el = 2 * r + half;
            const int e = ebase + el;
            const int src = esrc[e];
            const int dst = edst[e];
            if ((unsigned)src >= NN || (unsigned)dst >= NN) continue;

            const float4 bv = *(const float4*)(myB + el * H + cbase);
            const float4 pv = *(const float4*)(P + (size_t)src * H + cbase);

            float m0 = pv.x + bv.x, m1 = pv.y + bv.y;
            float m2 = pv.z + bv.z, m3 = pv.w + bv.w;
            m0 = fmaxf(m0, 0.1f * m0);
            m1 = fmaxf(m1, 0.1f * m1);
            m2 = fmaxf(m2, 0.1f * m2);
            m3 = fmaxf(m3, 0.1f * m3);

            float* dp = agg + (size_t)dst * H + cbase;
            asm volatile("red.global.add.v4.f32 [%0], {%1, %2, %3, %4};"
                         :: "l"(dp), "f"(m0), "f"(m1), "f"(m2), "f"(m3)
                         : "memory");
        }
        __syncwarp();
    }
}

// ---------------------------------------------------------------------------
// upd (HMMA): out = concat(h, agg) @ W1(128x64) + b1.  Split-fp16, K=128.
// ---------------------------------------------------------------------------
__global__ __launch_bounds__(256) void upd_kernel(const float* __restrict__ h,
                                                  const float* __restrict__ agg,
                                                  const float* __restrict__ w,
                                                  const float* __restrict__ b,
                                                  float* __restrict__ out) {
    __shared__ __half sWh[2 * H * H], sWl[2 * H * H];  // 16384 B each
    __shared__ __half sAh[32 * 16], sAl[32 * 16];      // 1024 B each
    __shared__ float  sOut[8][16 * 16];                // 8192 B
    __shared__ float  sBias[H];

    for (int i = threadIdx.x; i < 2 * H * H; i += 256) {
        float v = w[i];
        __half hi = __float2half(v);
        sWh[i] = hi;
        sWl[i] = __float2half(v - __half2float(hi));
    }
    if (threadIdx.x < H) sBias[threadIdx.x] = b[threadIdx.x];

    const int wid = threadIdx.x >> 5, lane = threadIdx.x & 31;
    const int warp_m = wid >> 2, warp_n = wid & 3;

    const int stg_r = (threadIdx.x * 2) >> 4;
    const int stg_c = (threadIdx.x * 2) & 15;

    for (int tile = blockIdx.x; tile < NN / 32; tile += gridDim.x) {
        const int nbase = tile * 32;
        wmma::fragment<wmma::accumulator, 16, 16, 16, float> fc;
        wmma::fill_fragment(fc, 0.f);

#pragma unroll
        for (int kc = 0; kc < 8; kc++) {
            __syncthreads();
            {   // stage concat(h, agg) chunk [32][16] as hi/lo
                const int k = kc * 16 + stg_c;
                const float* sp = (kc < 4)
                    ? (h   + (size_t)(nbase + stg_r) * H + k)
                    : (agg + (size_t)(nbase + stg_r) * H + (k - H));
                __half2 hh, hl;
                split2(sp[0], sp[1], hh, hl);
                *(__half2*)&sAh[stg_r * 16 + stg_c] = hh;
                *(__half2*)&sAl[stg_r * 16 + stg_c] = hl;
            }
            __syncthreads();

            wmma::fragment<wmma::matrix_a, 16, 16, 16, __half, wmma::row_major> fah, fal;
            wmma::load_matrix_sync(fah, &sAh[warp_m * 16 * 16], 16);
            wmma::load_matrix_sync(fal, &sAl[warp_m * 16 * 16], 16);
            wmma::fragment<wmma::matrix_b, 16, 16, 16, __half, wmma::row_major> fwh, fwl;
            wmma::load_matrix_sync(fwh, &sWh[(kc * 16) * H + warp_n * 16], H);
            wmma::load_matrix_sync(fwl, &sWl[(kc * 16) * H + warp_n * 16], H);
            wmma::mma_sync(fc, fah, fwh, fc);
            wmma::mma_sync(fc, fah, fwl, fc);
            wmma::mma_sync(fc, fal, fwh, fc);
        }

        wmma::store_matrix_sync(sOut[wid], fc, 16, wmma::mem_row_major);
        __syncwarp();
        {
            const int r = lane >> 1, c = (lane & 1) * 8;
            const int node = nbase + warp_m * 16 + r;
            const int col = warp_n * 16 + c;
            float4 v0 = *(float4*)&sOut[wid][r * 16 + c];
            float4 v1 = *(float4*)&sOut[wid][r * 16 + c + 4];
            const float* bp = &sBias[col];
            v0.x += bp[0]; v0.y += bp[1]; v0.z += bp[2]; v0.w += bp[3];
            v1.x += bp[4]; v1.y += bp[5]; v1.z += bp[6]; v1.w += bp[7];
            float* op = out + (size_t)node * H + col;
            *(float4*)op = v0;
            *(float4*)(op + 4) = v1;
        }
    }
}

// ---------------------------------------------------------------------------
extern "C" void kernel_launch(void* const* d_in, const int* in_sizes, int n_in,
                              void* d_out, int out_size) {
    const float* x      = (const float*)d_in[0];   // [100000, 75]
    const int*   eidx   = (const int*)d_in[1];     // [2, 1600000] (int64 -> int32)
    const float* eattr  = (const float*)d_in[2];   // [1600000, 16]
    const float* proj_w = (const float*)d_in[3];
    const float* proj_b = (const float*)d_in[4];
    const float* u2w    = (const float*)d_in[5];   // [3, 80, 64]
    const float* u2b    = (const float*)d_in[6];
    const float* u1w    = (const float*)d_in[7];   // [3, 128, 64]
    const float* u1b    = (const float*)d_in[8];
    float*       out    = (float*)d_out;           // [100000, 64]

    float *hA, *hB, *P, *agg;
    cudaGetSymbolAddress((void**)&hA, g_hA);
    cudaGetSymbolAddress((void**)&hB, g_hB);
    cudaGetSymbolAddress((void**)&P, g_P);
    cudaGetSymbolAddress((void**)&agg, g_agg);

    proj_kernel<<<592, 256>>>(x, proj_w, proj_b, hA);

    for (int l = 0; l < 3; l++) {
        const float* hin = (l == 1) ? hB : hA;          // l0:A, l1:B, l2:A
        float* hout = (l == 0) ? hB : ((l == 1) ? hA : out);
        const float* w2 = u2w + (size_t)l * 80 * 64;     // rows 0..63 = W2h, 64..79 = W2e
        pk_kernel<<<592, 256>>>(hin, w2, u2b + l * 64, P, agg);
        edge_kernel<<<1184, 256>>>(eidx, eidx + NE, eattr, w2 + 64 * 64, P, agg);
        upd_kernel<<<592, 256>>>(hin, agg, u1w + (size_t)l * 128 * 64, u1b + l * 64, hout);
    }
}

// round 10
// speedup vs baseline: 1.0543x; 1.0543x over previous
#include <cuda_runtime.h>
#include <cuda_fp16.h>
#include <mma.h>

using namespace nvcuda;

#define NN 100000
#define NE 1600000
#define IND 75
#define H 64
#define HB 16

// Scratch (allocation-free rule: __device__ globals)
__device__ __align__(256) float g_hA[NN * H];
__device__ __align__(256) float g_hB[NN * H];
__device__ __align__(256) float g_P[NN * H];
__device__ __align__(256) float g_agg[NN * H];

// ---------------------------------------------------------------------------
// proj: out = x @ W(75x64) + b     (run once)
// ---------------------------------------------------------------------------
__global__ __launch_bounds__(256) void proj_kernel(const float* __restrict__ x,
                                                   const float* __restrict__ w,
                                                   const float* __restrict__ b,
                                                   float* __restrict__ out) {
    __shared__ float sW[IND][H];
    __shared__ float sA[32][IND + 1];
    for (int i = threadIdx.x; i < IND * H; i += 256) sW[i / H][i % H] = w[i];

    const int lane = threadIdx.x & 31, wid = threadIdx.x >> 5;
    const int nl = lane & 3, cg = lane >> 2;
    const int myn = wid * 4 + nl;
    const float4 bb0 = *(const float4*)&b[cg * 8];
    const float4 bb1 = *(const float4*)&b[cg * 8 + 4];

    for (int tile = blockIdx.x; tile < NN / 32; tile += gridDim.x) {
        const int base = tile * 32;
        __syncthreads();
        for (int i = threadIdx.x; i < 32 * IND; i += 256)
            sA[i / IND][i % IND] = x[(size_t)base * IND + i];
        __syncthreads();

        float acc[8] = {bb0.x, bb0.y, bb0.z, bb0.w, bb1.x, bb1.y, bb1.z, bb1.w};
#pragma unroll 5
        for (int k = 0; k < IND; k++) {
            const float a = sA[myn][k];
            const float4 w0 = *(const float4*)&sW[k][cg * 8];
            const float4 w1 = *(const float4*)&sW[k][cg * 8 + 4];
            acc[0] += a * w0.x; acc[1] += a * w0.y; acc[2] += a * w0.z; acc[3] += a * w0.w;
            acc[4] += a * w1.x; acc[5] += a * w1.y; acc[6] += a * w1.z; acc[7] += a * w1.w;
        }
        const size_t o = (size_t)(base + myn) * H + cg * 8;
        *(float4*)&out[o]     = make_float4(acc[0], acc[1], acc[2], acc[3]);
        *(float4*)&out[o + 4] = make_float4(acc[4], acc[5], acc[6], acc[7]);
    }
}

// ---------------------------------------------------------------------------
// Split-fp16 staging: 8 consecutive floats -> hi/lo fp16 rows.
// thread covers row = tid/8, cols (tid%8)*8 .. +7
// ---------------------------------------------------------------------------
__device__ __forceinline__ void stage8(const float* __restrict__ sp,
                                       __half* __restrict__ dh,
                                       __half* __restrict__ dl) {
    const float4 v0 = *(const float4*)sp;
    const float4 v1 = *(const float4*)(sp + 4);
    float vv[8] = {v0.x, v0.y, v0.z, v0.w, v1.x, v1.y, v1.z, v1.w};
#pragma unroll
    for (int i = 0; i < 4; i++) {
        __half h0 = __float2half(vv[2 * i]), h1 = __float2half(vv[2 * i + 1]);
        *(__half2*)&dh[2 * i] = __halves2half2(h0, h1);
        *(__half2*)&dl[2 * i] = __halves2half2(
            __float2half(vv[2 * i] - __half2float(h0)),
            __float2half(vv[2 * i + 1] - __half2float(h1)));
    }
}

// ---------------------------------------------------------------------------
// pk (HMMA v2): P = h @ W2h(64x64) + b2, zero agg.
// 32-node x 64-col tile, 8 warps = 2m x 4n grid of m16n16 outputs.
// W fragments hoisted to registers; bias via extra MMA; direct global store.
// 2 barriers per tile.
// ---------------------------------------------------------------------------
__global__ __launch_bounds__(256) void pk_kernel(const float* __restrict__ h,
                                                 const float* __restrict__ w,
                                                 const float* __restrict__ b,
                                                 float* __restrict__ P,
                                                 float* __restrict__ agg) {
    __shared__ __half sWh[H * H], sWl[H * H];    // 8 KB each
    __shared__ __half sWext[16 * H];             // 2 KB: row0=bias_hi, row1=bias_lo
    __shared__ __half sAext[32 * 16];            // 1 KB: cols 0,1 = 1.0
    __shared__ __half sAh[32 * H], sAl[32 * H];  // 4 KB each

    for (int i = threadIdx.x; i < H * H; i += 256) {
        float v = w[i];
        __half hi = __float2half(v);
        sWh[i] = hi;
        sWl[i] = __float2half(v - __half2float(hi));
    }
    for (int i = threadIdx.x; i < 16 * H; i += 256) {
        const int r = i >> 6, c = i & 63;
        __half v = __float2half(0.f);
        if (r == 0) v = __float2half(b[c]);
        else if (r == 1) {
            float bb = b[c];
            v = __float2half(bb - __half2float(__float2half(bb)));
        }
        sWext[i] = v;
    }
    for (int i = threadIdx.x; i < 32 * 16; i += 256)
        sAext[i] = __float2half(((i & 15) < 2) ? 1.f : 0.f);
    __syncthreads();

    const int wid = threadIdx.x >> 5;
    const int warp_m = wid >> 2, warp_n = wid & 3;
    const int stg_r = threadIdx.x >> 3, stg_c = (threadIdx.x & 7) * 8;

    // hoisted fragments
    wmma::fragment<wmma::matrix_b, 16, 16, 16, __half, wmma::row_major> fwh[4], fwl[4], fwb;
    wmma::fragment<wmma::matrix_a, 16, 16, 16, __half, wmma::row_major> faext;
#pragma unroll
    for (int kc = 0; kc < 4; kc++) {
        wmma::load_matrix_sync(fwh[kc], &sWh[(kc * 16) * H + warp_n * 16], H);
        wmma::load_matrix_sync(fwl[kc], &sWl[(kc * 16) * H + warp_n * 16], H);
    }
    wmma::load_matrix_sync(fwb, &sWext[warp_n * 16], H);
    wmma::load_matrix_sync(faext, &sAext[warp_m * 16 * 16], 16);

    const float4 z4 = make_float4(0.f, 0.f, 0.f, 0.f);

    for (int tile = blockIdx.x; tile < NN / 32; tile += gridDim.x) {
        const int nbase = tile * 32;
        wmma::fragment<wmma::accumulator, 16, 16, 16, float> fc;
        wmma::fill_fragment(fc, 0.f);

        __syncthreads();
        stage8(h + (size_t)(nbase + stg_r) * H + stg_c,
               &sAh[stg_r * H + stg_c], &sAl[stg_r * H + stg_c]);
        __syncthreads();

#pragma unroll
        for (int kc = 0; kc < 4; kc++) {
            wmma::fragment<wmma::matrix_a, 16, 16, 16, __half, wmma::row_major> fah, fal;
            wmma::load_matrix_sync(fah, &sAh[warp_m * 16 * H + kc * 16], H);
            wmma::load_matrix_sync(fal, &sAl[warp_m * 16 * H + kc * 16], H);
            wmma::mma_sync(fc, fah, fwh[kc], fc);
            wmma::mma_sync(fc, fah, fwl[kc], fc);
            wmma::mma_sync(fc, fal, fwh[kc], fc);
        }
        wmma::mma_sync(fc, faext, fwb, fc);   // + bias

        wmma::store_matrix_sync(P + (size_t)(nbase + warp_m * 16) * H + warp_n * 16,
                                fc, H, wmma::mem_row_major);

        float4* ap = (float4*)(agg + (size_t)nbase * H) + threadIdx.x * 2;
        ap[0] = z4; ap[1] = z4;
    }
}

// ---------------------------------------------------------------------------
// edge (HMMA, from R8 unchanged): warp handles 16 edges.
// ---------------------------------------------------------------------------
__global__ __launch_bounds__(256) void edge_kernel(const int* __restrict__ esrc,
                                                   const int* __restrict__ edst,
                                                   const float* __restrict__ eattr,
                                                   const float* __restrict__ w2e,
                                                   const float* __restrict__ P,
                                                   float* __restrict__ agg) {
    __shared__ __half sW[HB * H];              // 2048 B
    __shared__ __half sA[8][HB * HB];          // 8 x 512 B
    __shared__ float  sB[8][HB * H];           // 8 x 4096 B

    for (int i = threadIdx.x; i < HB * H; i += 256) sW[i] = __float2half(w2e[i]);
    __syncthreads();

    const int lane = threadIdx.x & 31, wid = threadIdx.x >> 5;
    const int half = lane >> 4, hl = lane & 15;
    const int cbase = hl * 4;

    wmma::fragment<wmma::matrix_b, 16, 16, 16, __half, wmma::row_major> fw[4];
#pragma unroll
    for (int nt = 0; nt < 4; nt++)
        wmma::load_matrix_sync(fw[nt], &sW[nt * 16], H);

    __half* const myA = sA[wid];
    float*  const myB = sB[wid];
    const int arow = lane >> 1, acol = (lane & 1) * 8;

    const int gw = blockIdx.x * 8 + wid;
    const int nw = gridDim.x * 8;

    for (int t = gw; t < NE / 16; t += nw) {
        const int ebase = t * 16;
        {
            const float4* src = (const float4*)(eattr + (size_t)(ebase + arow) * HB + acol);
            const float4 v0 = src[0], v1 = src[1];
            __half2 h0 = __floats2half2_rn(v0.x, v0.y);
            __half2 h1 = __floats2half2_rn(v0.z, v0.w);
            __half2 h2 = __floats2half2_rn(v1.x, v1.y);
            __half2 h3 = __floats2half2_rn(v1.z, v1.w);
            uint4 pk;
            pk.x = *(unsigned*)&h0; pk.y = *(unsigned*)&h1;
            pk.z = *(unsigned*)&h2; pk.w = *(unsigned*)&h3;
            *(uint4*)(myA + arow * HB + acol) = pk;
        }
        __syncwarp();

        wmma::fragment<wmma::matrix_a, 16, 16, 16, __half, wmma::row_major> fa;
        wmma::load_matrix_sync(fa, myA, HB);
#pragma unroll
        for (int nt = 0; nt < 4; nt++) {
            wmma::fragment<wmma::accumulator, 16, 16, 16, float> fc;
            wmma::fill_fragment(fc, 0.f);
            wmma::mma_sync(fc, fa, fw[nt], fc);
            wmma::store_matrix_sync(&myB[nt * 16], fc, H, wmma::mem_row_major);
        }
        __syncwarp();

#pragma unroll
        for (int r = 0; r < 8; r++) {
            const int el = 2 * r + half;
            const int e = ebase + el;
            const int src = esrc[e];
            const int dst = edst[e];
            if ((unsigned)src >= NN || (unsigned)dst >= NN) continue;

            const float4 bv = *(const float4*)(myB + el * H + cbase);
            const float4 pv = *(const float4*)(P + (size_t)src * H + cbase);

            float m0 = pv.x + bv.x, m1 = pv.y + bv.y;
            float m2 = pv.z + bv.z, m3 = pv.w + bv.w;
            m0 = fmaxf(m0, 0.1f * m0);
            m1 = fmaxf(m1, 0.1f * m1);
            m2 = fmaxf(m2, 0.1f * m2);
            m3 = fmaxf(m3, 0.1f * m3);

            float* dp = agg + (size_t)dst * H + cbase;
            asm volatile("red.global.add.v4.f32 [%0], {%1, %2, %3, %4};"
                         :: "l"(dp), "f"(m0), "f"(m1), "f"(m2), "f"(m3)
                         : "memory");
        }
        __syncwarp();
    }
}

// ---------------------------------------------------------------------------
// upd (HMMA v2): out = concat(h, agg) @ W1(128x64) + b1.
// K=128 staged in two 64-col chunks (4 barriers/tile); W frags hoisted;
// bias via extra MMA; direct global store.
// ---------------------------------------------------------------------------
__global__ __launch_bounds__(256) void upd_kernel(const float* __restrict__ h,
                                                  const float* __restrict__ agg,
                                                  const float* __restrict__ w,
                                                  const float* __restrict__ b,
                                                  float* __restrict__ out) {
    __shared__ __half sWh[2 * H * H], sWl[2 * H * H];  // 16 KB each
    __shared__ __half sWext[16 * H];                   // 2 KB
    __shared__ __half sAext[32 * 16];                  // 1 KB
    __shared__ __half sAh[32 * H], sAl[32 * H];        // 4 KB each

    for (int i = threadIdx.x; i < 2 * H * H; i += 256) {
        float v = w[i];
        __half hi = __float2half(v);
        sWh[i] = hi;
        sWl[i] = __float2half(v - __half2float(hi));
    }
    for (int i = threadIdx.x; i < 16 * H; i += 256) {
        const int r = i >> 6, c = i & 63;
        __half v = __float2half(0.f);
        if (r == 0) v = __float2half(b[c]);
        else if (r == 1) {
            float bb = b[c];
            v = __float2half(bb - __half2float(__float2half(bb)));
        }
        sWext[i] = v;
    }
    for (int i = threadIdx.x; i < 32 * 16; i += 256)
        sAext[i] = __float2half(((i & 15) < 2) ? 1.f : 0.f);
    __syncthreads();

    const int wid = threadIdx.x >> 5;
    const int warp_m = wid >> 2, warp_n = wid & 3;
    const int stg_r = threadIdx.x >> 3, stg_c = (threadIdx.x & 7) * 8;

    wmma::fragment<wmma::matrix_b, 16, 16, 16, __half, wmma::row_major> fwh[8], fwl[8], fwb;
    wmma::fragment<wmma::matrix_a, 16, 16, 16, __half, wmma::row_major> faext;
#pragma unroll
    for (int kc = 0; kc < 8; kc++) {
        wmma::load_matrix_sync(fwh[kc], &sWh[(kc * 16) * H + warp_n * 16], H);
        wmma::load_matrix_sync(fwl[kc], &sWl[(kc * 16) * H + warp_n * 16], H);
    }
    wmma::load_matrix_sync(fwb, &sWext[warp_n * 16], H);
    wmma::load_matrix_sync(faext, &sAext[warp_m * 16 * 16], 16);

    for (int tile = blockIdx.x; tile < NN / 32; tile += gridDim.x) {
        const int nbase = tile * 32;
        wmma::fragment<wmma::accumulator, 16, 16, 16, float> fc;
        wmma::fill_fragment(fc, 0.f);

#pragma unroll
        for (int ch = 0; ch < 2; ch++) {
            const float* srcm = (ch == 0) ? h : agg;
            __syncthreads();
            stage8(srcm + (size_t)(nbase + stg_r) * H + stg_c,
                   &sAh[stg_r * H + stg_c], &sAl[stg_r * H + stg_c]);
            __syncthreads();

#pragma unroll
            for (int kc = 0; kc < 4; kc++) {
                const int gk = ch * 4 + kc;
                wmma::fragment<wmma::matrix_a, 16, 16, 16, __half, wmma::row_major> fah, fal;
                wmma::load_matrix_sync(fah, &sAh[warp_m * 16 * H + kc * 16], H);
                wmma::load_matrix_sync(fal, &sAl[warp_m * 16 * H + kc * 16], H);
                wmma::mma_sync(fc, fah, fwh[gk], fc);
                wmma::mma_sync(fc, fah, fwl[gk], fc);
                wmma::mma_sync(fc, fal, fwh[gk], fc);
            }
        }
        wmma::mma_sync(fc, faext, fwb, fc);   // + bias

        wmma::store_matrix_sync(out + (size_t)(nbase + warp_m * 16) * H + warp_n * 16,
                                fc, H, wmma::mem_row_major);
    }
}

// ---------------------------------------------------------------------------
extern "C" void kernel_launch(void* const* d_in, const int* in_sizes, int n_in,
                              void* d_out, int out_size) {
    const float* x      = (const float*)d_in[0];   // [100000, 75]
    const int*   eidx   = (const int*)d_in[1];     // [2, 1600000] (int64 -> int32)
    const float* eattr  = (const float*)d_in[2];   // [1600000, 16]
    const float* proj_w = (const float*)d_in[3];
    const float* proj_b = (const float*)d_in[4];
    const float* u2w    = (const float*)d_in[5];   // [3, 80, 64]
    const float* u2b    = (const float*)d_in[6];
    const float* u1w    = (const float*)d_in[7];   // [3, 128, 64]
    const float* u1b    = (const float*)d_in[8];
    float*       out    = (float*)d_out;           // [100000, 64]

    float *hA, *hB, *P, *agg;
    cudaGetSymbolAddress((void**)&hA, g_hA);
    cudaGetSymbolAddress((void**)&hB, g_hB);
    cudaGetSymbolAddress((void**)&P, g_P);
    cudaGetSymbolAddress((void**)&agg, g_agg);

    proj_kernel<<<592, 256>>>(x, proj_w, proj_b, hA);

    for (int l = 0; l < 3; l++) {
        const float* hin = (l == 1) ? hB : hA;          // l0:A, l1:B, l2:A
        float* hout = (l == 0) ? hB : ((l == 1) ? hA : out);
        const float* w2 = u2w + (size_t)l * 80 * 64;     // rows 0..63 = W2h, 64..79 = W2e
        pk_kernel<<<592, 256>>>(hin, w2, u2b + l * 64, P, agg);
        edge_kernel<<<1184, 256>>>(eidx, eidx + NE, eattr, w2 + 64 * 64, P, agg);
        upd_kernel<<<592, 256>>>(hin, agg, u1w + (size_t)l * 128 * 64, u1b + l * 64, hout);
    }
}

// round 11
// speedup vs baseline: 1.0988x; 1.0421x over previous
#include <cuda_runtime.h>
#include <cuda_fp16.h>
#include <mma.h>

using namespace nvcuda;

#define NN 100000
#define NE 1600000
#define IND 75
#define H 64
#define HB 16

// Scratch (allocation-free rule: __device__ globals)
__device__ __align__(256) float  g_hA[NN * H];
__device__ __align__(256) float  g_hB[NN * H];
__device__ __align__(256) __half g_P[NN * H];      // fp16 P
__device__ __align__(256) float  g_agg[NN * H];

// ---- f32x2 packed helpers -------------------------------------------------
typedef unsigned long long u64t;
__device__ __forceinline__ u64t pk2(float lo, float hi) {
    u64t r; asm("mov.b64 %0, {%1, %2};" : "=l"(r) : "f"(lo), "f"(hi)); return r;
}
__device__ __forceinline__ void upk2(u64t v, float& lo, float& hi) {
    asm("mov.b64 {%0, %1}, %2;" : "=f"(lo), "=f"(hi) : "l"(v));
}
__device__ __forceinline__ u64t fma2(u64t a, u64t b, u64t c) {
    u64t d; asm("fma.rn.f32x2 %0, %1, %2, %3;" : "=l"(d) : "l"(a), "l"(b), "l"(c)); return d;
}

// ---------------------------------------------------------------------------
// proj: out = x @ W(75x64) + b     (run once)
// ---------------------------------------------------------------------------
__global__ __launch_bounds__(256) void proj_kernel(const float* __restrict__ x,
                                                   const float* __restrict__ w,
                                                   const float* __restrict__ b,
                                                   float* __restrict__ out) {
    __shared__ float sW[IND][H];
    __shared__ float sA[32][IND + 1];
    for (int i = threadIdx.x; i < IND * H; i += 256) sW[i / H][i % H] = w[i];

    const int lane = threadIdx.x & 31, wid = threadIdx.x >> 5;
    const int nl = lane & 3, cg = lane >> 2;
    const int myn = wid * 4 + nl;
    const float4 bb0 = *(const float4*)&b[cg * 8];
    const float4 bb1 = *(const float4*)&b[cg * 8 + 4];

    for (int tile = blockIdx.x; tile < NN / 32; tile += gridDim.x) {
        const int base = tile * 32;
        __syncthreads();
        for (int i = threadIdx.x; i < 32 * IND; i += 256)
            sA[i / IND][i % IND] = x[(size_t)base * IND + i];
        __syncthreads();

        float acc[8] = {bb0.x, bb0.y, bb0.z, bb0.w, bb1.x, bb1.y, bb1.z, bb1.w};
#pragma unroll 5
        for (int k = 0; k < IND; k++) {
            const float a = sA[myn][k];
            const float4 w0 = *(const float4*)&sW[k][cg * 8];
            const float4 w1 = *(const float4*)&sW[k][cg * 8 + 4];
            acc[0] += a * w0.x; acc[1] += a * w0.y; acc[2] += a * w0.z; acc[3] += a * w0.w;
            acc[4] += a * w1.x; acc[5] += a * w1.y; acc[6] += a * w1.z; acc[7] += a * w1.w;
        }
        const size_t o = (size_t)(base + myn) * H + cg * 8;
        *(float4*)&out[o]     = make_float4(acc[0], acc[1], acc[2], acc[3]);
        *(float4*)&out[o + 4] = make_float4(acc[4], acc[5], acc[6], acc[7]);
    }
}

// ---------------------------------------------------------------------------
// pk (scalar + f32x2): P(fp16) = h @ W2h(64x64) + b2, zero agg (fused).
// ---------------------------------------------------------------------------
__global__ __launch_bounds__(256) void pk_kernel(const float* __restrict__ h,
                                                 const float* __restrict__ w,
                                                 const float* __restrict__ b,
                                                 __half* __restrict__ P,
                                                 float* __restrict__ agg) {
    __shared__ float sW[H][H];
    __shared__ float sA[32][H + 1];
    for (int i = threadIdx.x; i < H * H; i += 256) sW[i >> 6][i & 63] = w[i];

    const int lane = threadIdx.x & 31, wid = threadIdx.x >> 5;
    const int nl = lane & 3, cg = lane >> 2;
    const int myn = wid * 4 + nl;
    const float4 bb0 = *(const float4*)&b[cg * 8];
    const float4 bb1 = *(const float4*)&b[cg * 8 + 4];
    const float4 z4 = make_float4(0.f, 0.f, 0.f, 0.f);

    for (int tile = blockIdx.x; tile < NN / 32; tile += gridDim.x) {
        const int base = tile * 32;
        __syncthreads();
        for (int i = threadIdx.x; i < 32 * H; i += 256)
            sA[i >> 6][i & 63] = h[(size_t)base * H + i];
        __syncthreads();

        u64t acc[4] = {pk2(bb0.x, bb0.y), pk2(bb0.z, bb0.w),
                       pk2(bb1.x, bb1.y), pk2(bb1.z, bb1.w)};
#pragma unroll 8
        for (int k = 0; k < H; k++) {
            const float a = sA[myn][k];
            const u64t aa = pk2(a, a);
            const ulonglong2 w0 = *(const ulonglong2*)&sW[k][cg * 8];
            const ulonglong2 w1 = *(const ulonglong2*)&sW[k][cg * 8 + 4];
            acc[0] = fma2(aa, w0.x, acc[0]);
            acc[1] = fma2(aa, w0.y, acc[1]);
            acc[2] = fma2(aa, w1.x, acc[2]);
            acc[3] = fma2(aa, w1.y, acc[3]);
        }
        // convert to fp16 pairs and store (8 halves = 16B)
        float l0, h0, l1, h1, l2, h2, l3, h3;
        upk2(acc[0], l0, h0); upk2(acc[1], l1, h1);
        upk2(acc[2], l2, h2); upk2(acc[3], l3, h3);
        __half2 p0 = __floats2half2_rn(l0, h0);
        __half2 p1 = __floats2half2_rn(l1, h1);
        __half2 p2 = __floats2half2_rn(l2, h2);
        __half2 p3 = __floats2half2_rn(l3, h3);
        uint4 pr;
        pr.x = *(unsigned*)&p0; pr.y = *(unsigned*)&p1;
        pr.z = *(unsigned*)&p2; pr.w = *(unsigned*)&p3;
        *(uint4*)(P + (size_t)(base + myn) * H + cg * 8) = pr;

        const size_t o = (size_t)(base + myn) * H + cg * 8;
        *(float4*)&agg[o]     = z4;
        *(float4*)&agg[o + 4] = z4;
    }
}

// ---------------------------------------------------------------------------
// edge (HMMA): warp handles 16 edges; eattr -> fp16 -> wmma vs reg-resident
// W2e; scatter agg[dst] +=red leakyrelu(P_fp16[src] + Brow).
// ---------------------------------------------------------------------------
__global__ __launch_bounds__(256) void edge_kernel(const int* __restrict__ esrc,
                                                   const int* __restrict__ edst,
                                                   const float* __restrict__ eattr,
                                                   const float* __restrict__ w2e,
                                                   const __half* __restrict__ P,
                                                   float* __restrict__ agg) {
    __shared__ __half sW[HB * H];              // 2048 B
    __shared__ __half sA[8][HB * HB];          // 8 x 512 B
    __shared__ float  sB[8][HB * H];           // 8 x 4096 B

    for (int i = threadIdx.x; i < HB * H; i += 256) sW[i] = __float2half(w2e[i]);
    __syncthreads();

    const int lane = threadIdx.x & 31, wid = threadIdx.x >> 5;
    const int half = lane >> 4, hl = lane & 15;
    const int cbase = hl * 4;

    wmma::fragment<wmma::matrix_b, 16, 16, 16, __half, wmma::row_major> fw[4];
#pragma unroll
    for (int nt = 0; nt < 4; nt++)
        wmma::load_matrix_sync(fw[nt], &sW[nt * 16], H);

    __half* const myA = sA[wid];
    float*  const myB = sB[wid];
    const int arow = lane >> 1, acol = (lane & 1) * 8;

    const int gw = blockIdx.x * 8 + wid;
    const int nw = gridDim.x * 8;

    for (int t = gw; t < NE / 16; t += nw) {
        const int ebase = t * 16;
        {
            const float4* src = (const float4*)(eattr + (size_t)(ebase + arow) * HB + acol);
            const float4 v0 = src[0], v1 = src[1];
            __half2 h0 = __floats2half2_rn(v0.x, v0.y);
            __half2 h1 = __floats2half2_rn(v0.z, v0.w);
            __half2 h2 = __floats2half2_rn(v1.x, v1.y);
            __half2 h3 = __floats2half2_rn(v1.z, v1.w);
            uint4 pk;
            pk.x = *(unsigned*)&h0; pk.y = *(unsigned*)&h1;
            pk.z = *(unsigned*)&h2; pk.w = *(unsigned*)&h3;
            *(uint4*)(myA + arow * HB + acol) = pk;
        }
        __syncwarp();

        wmma::fragment<wmma::matrix_a, 16, 16, 16, __half, wmma::row_major> fa;
        wmma::load_matrix_sync(fa, myA, HB);
#pragma unroll
        for (int nt = 0; nt < 4; nt++) {
            wmma::fragment<wmma::accumulator, 16, 16, 16, float> fc;
            wmma::fill_fragment(fc, 0.f);
            wmma::mma_sync(fc, fa, fw[nt], fc);
            wmma::store_matrix_sync(&myB[nt * 16], fc, H, wmma::mem_row_major);
        }
        __syncwarp();

#pragma unroll
        for (int r = 0; r < 8; r++) {
            const int el = 2 * r + half;
            const int e = ebase + el;
            const int src = esrc[e];
            const int dst = edst[e];
            if ((unsigned)src >= NN || (unsigned)dst >= NN) continue;

            const float4 bv = *(const float4*)(myB + el * H + cbase);
            const uint2 praw = *(const uint2*)(P + (size_t)src * H + cbase);
            const float2 pa = __half22float2(*(const __half2*)&praw.x);
            const float2 pb = __half22float2(*(const __half2*)&praw.y);

            float m0 = pa.x + bv.x, m1 = pa.y + bv.y;
            float m2 = pb.x + bv.z, m3 = pb.y + bv.w;
            m0 = fmaxf(m0, 0.1f * m0);
            m1 = fmaxf(m1, 0.1f * m1);
            m2 = fmaxf(m2, 0.1f * m2);
            m3 = fmaxf(m3, 0.1f * m3);

            float* dp = agg + (size_t)dst * H + cbase;
            asm volatile("red.global.add.v4.f32 [%0], {%1, %2, %3, %4};"
                         :: "l"(dp), "f"(m0), "f"(m1), "f"(m2), "f"(m3)
                         : "memory");
        }
        __syncwarp();
    }
}

// ---------------------------------------------------------------------------
// upd (scalar + f32x2): out = concat(h, agg) @ W1(128x64) + b1
// ---------------------------------------------------------------------------
__global__ __launch_bounds__(256) void upd_kernel(const float* __restrict__ h,
                                                  const float* __restrict__ agg,
                                                  const float* __restrict__ w,
                                                  const float* __restrict__ b,
                                                  float* __restrict__ out) {
    __shared__ float sW[2 * H][H];   // 32768 B
    __shared__ float sA[32][2 * H];  // 16384 B, XOR-swizzled by (row&3)<<3
    for (int i = threadIdx.x; i < 2 * H * H; i += 256) sW[i >> 6][i & 63] = w[i];

    const int lane = threadIdx.x & 31, wid = threadIdx.x >> 5;
    const int nl = lane & 3, cg = lane >> 2;
    const int myn = wid * 4 + nl;
    const int swz = nl << 3;
    const float4 bb0 = *(const float4*)&b[cg * 8];
    const float4 bb1 = *(const float4*)&b[cg * 8 + 4];

    for (int tile = blockIdx.x; tile < NN / 32; tile += gridDim.x) {
        const int base = tile * 32;
        __syncthreads();
        for (int i = threadIdx.x; i < 32 * H; i += 256) {
            const int r = i >> 6, c = i & 63;
            const int s = (r & 3) << 3;
            sA[r][c ^ s]        = h[(size_t)base * H + i];
            sA[r][(c + 64) ^ s] = agg[(size_t)base * H + i];
        }
        __syncthreads();

        u64t acc[4] = {pk2(bb0.x, bb0.y), pk2(bb0.z, bb0.w),
                       pk2(bb1.x, bb1.y), pk2(bb1.z, bb1.w)};
#pragma unroll 8
        for (int k = 0; k < 2 * H; k++) {
            const float a = sA[myn][k ^ swz];
            const u64t aa = pk2(a, a);
            const ulonglong2 w0 = *(const ulonglong2*)&sW[k][cg * 8];
            const ulonglong2 w1 = *(const ulonglong2*)&sW[k][cg * 8 + 4];
            acc[0] = fma2(aa, w0.x, acc[0]);
            acc[1] = fma2(aa, w0.y, acc[1]);
            acc[2] = fma2(aa, w1.x, acc[2]);
            acc[3] = fma2(aa, w1.y, acc[3]);
        }
        float o0, o1, o2, o3, o4, o5, o6, o7;
        upk2(acc[0], o0, o1); upk2(acc[1], o2, o3);
        upk2(acc[2], o4, o5); upk2(acc[3], o6, o7);
        const size_t o = (size_t)(base + myn) * H + cg * 8;
        *(float4*)&out[o]     = make_float4(o0, o1, o2, o3);
        *(float4*)&out[o + 4] = make_float4(o4, o5, o6, o7);
    }
}

// ---------------------------------------------------------------------------
extern "C" void kernel_launch(void* const* d_in, const int* in_sizes, int n_in,
                              void* d_out, int out_size) {
    const float* x      = (const float*)d_in[0];   // [100000, 75]
    const int*   eidx   = (const int*)d_in[1];     // [2, 1600000] (int64 -> int32)
    const float* eattr  = (const float*)d_in[2];   // [1600000, 16]
    const float* proj_w = (const float*)d_in[3];
    const float* proj_b = (const float*)d_in[4];
    const float* u2w    = (const float*)d_in[5];   // [3, 80, 64]
    const float* u2b    = (const float*)d_in[6];
    const float* u1w    = (const float*)d_in[7];   // [3, 128, 64]
    const float* u1b    = (const float*)d_in[8];
    float*       out    = (float*)d_out;           // [100000, 64]

    float *hA, *hB, *agg;
    __half* P;
    cudaGetSymbolAddress((void**)&hA, g_hA);
    cudaGetSymbolAddress((void**)&hB, g_hB);
    cudaGetSymbolAddress((void**)&P, g_P);
    cudaGetSymbolAddress((void**)&agg, g_agg);

    proj_kernel<<<592, 256>>>(x, proj_w, proj_b, hA);

    for (int l = 0; l < 3; l++) {
        const float* hin = (l == 1) ? hB : hA;          // l0:A, l1:B, l2:A
        float* hout = (l == 0) ? hB : ((l == 1) ? hA : out);
        const float* w2 = u2w + (size_t)l * 80 * 64;     // rows 0..63 = W2h, 64..79 = W2e
        pk_kernel<<<592, 256>>>(hin, w2, u2b + l * 64, P, agg);
        edge_kernel<<<1184, 256>>>(eidx, eidx + NE, eattr, w2 + 64 * 64, P, agg);
        upd_kernel<<<592, 256>>>(hin, agg, u1w + (size_t)l * 128 * 64, u1b + l * 64, hout);
    }
}